// round 8
// baseline (speedup 1.0000x reference)
#include <cuda_runtime.h>
#include <cstdint>

// ===================== problem constants =====================
#define N_TOK 8192
#define DIM   128
#define NB2   144                 // padded N: 128 proj cols + 1 rowsum + 15 pad (tiles of 8)
#define KT    32                  // fp32 K elems per stage
#define NITER (N_TOK / KT)        // 256
#define ROWF  36                  // floats per padded smem row (144 B, conflict-free)
#define A_TILE_F (128 * ROWF)     // 4608 floats
#define B_TILE_F (NB2 * ROWF)     // 5184 floats
#define STAGE_F  (A_TILE_F + B_TILE_F)          // 9792 floats = 39168 B
#define SMEM_MAIN (1024 + 4 * STAGE_F * 4)      // 157696 B
#define PREP_SMEM ((64 * 129 + 128 * 129) * 4)  // 99072 B

// ===================== device scratch (no allocations allowed) ==============
// g_B[p]: rows 0..127 = (h0 @ W[:, :128]^T)^T  (tf32-RN), row 128 = ones,
//         rows 129..143 stay zero (never written; .bss zero-init) -> padded N cols ignored.
__device__ float g_B[2][NB2][N_TOK];
__device__ float g_S[2][N_TOK][DIM];   // self term h0 @ W[:,128:]^T (fp32)

// ===================== helpers =====================
__device__ __forceinline__ uint32_t smem_u32(const void* p) {
    uint32_t a;
    asm("{ .reg .u64 t; cvta.to.shared.u64 t, %1; cvt.u32.u64 %0, t; }" : "=r"(a) : "l"(p));
    return a;
}

#define CP_ASYNC16(dst, src) \
    asm volatile("cp.async.cg.shared.global [%0], [%1], 16;" :: "r"(dst), "l"(src) : "memory")
#define CP_COMMIT() asm volatile("cp.async.commit_group;" ::: "memory")
#define CP_WAITG(n) asm volatile("cp.async.wait_group %0;" :: "n"(n) : "memory")

// m16n8k8 tf32 MMA (SIMT tensor core path, plain sm_80+ PTX -> works on compute_103)
__device__ __forceinline__ void mma_tf32(float* d, const float* a, const float* b) {
    asm volatile(
        "mma.sync.aligned.m16n8k8.row.col.f32.tf32.tf32.f32 "
        "{%0,%1,%2,%3}, {%4,%5,%6,%7}, {%8,%9}, {%0,%1,%2,%3};"
        : "+f"(d[0]), "+f"(d[1]), "+f"(d[2]), "+f"(d[3])
        : "r"(__float_as_uint(a[0])), "r"(__float_as_uint(a[1])),
          "r"(__float_as_uint(a[2])), "r"(__float_as_uint(a[3])),
          "r"(__float_as_uint(b[0])), "r"(__float_as_uint(b[1])));
}

// ===================== prep: G = h0@W[:, :128]^T -> g_B (tf32-RN), S = h0@W[:,128:]^T ======
// grid (128, 4): x = 64-row k-chunk of h0; y = (p<<1)|half. 256 threads, 4x8 reg tiles.
__global__ void __launch_bounds__(256, 2) prep_kernel(const float* __restrict__ h0,
                                                      const float* __restrict__ Wpos,
                                                      const float* __restrict__ Wneg) {
    extern __shared__ float psm[];
    float* h0s = psm;               // [64][129]
    float* ws  = psm + 64 * 129;    // [128][129]

    int mode = blockIdx.y;
    int p = mode >> 1, half = mode & 1;
    const float* W = p ? Wneg : Wpos;
    int k0 = blockIdx.x * 64;
    int t = threadIdx.x;

    for (int i = t; i < 64 * 128; i += 256) {
        int r = i >> 7, c = i & 127;
        h0s[r * 129 + c] = h0[(k0 + r) * DIM + c];
    }
    for (int i = t; i < 128 * 128; i += 256) {
        int n = i >> 7, d = i & 127;
        ws[n * 129 + d] = W[n * 256 + half * 128 + d];
    }
    __syncthreads();

    int tx = t & 15, ty = t >> 4;
    float acc[4][8];
#pragma unroll
    for (int i = 0; i < 4; i++)
#pragma unroll
        for (int j = 0; j < 8; j++) acc[i][j] = 0.f;

#pragma unroll 4
    for (int d = 0; d < 128; d++) {
        float a[4], b[8];
#pragma unroll
        for (int i = 0; i < 4; i++) a[i] = h0s[(tx + 16 * i) * 129 + d];
#pragma unroll
        for (int j = 0; j < 8; j++) b[j] = ws[(ty + 16 * j) * 129 + d];
#pragma unroll
        for (int i = 0; i < 4; i++)
#pragma unroll
            for (int j = 0; j < 8; j++) acc[i][j] = fmaf(a[i], b[j], acc[i][j]);
    }

    if (half == 0) {
        // g_B[p][n][k] = round_rn_tf32(G[k][n])  (coalesced over tx = k)
#pragma unroll
        for (int j = 0; j < 8; j++) {
            int n = ty + 16 * j;
            float* dst = &g_B[p][n][k0 + tx];
#pragma unroll
            for (int i = 0; i < 4; i++) {
                uint32_t tv;
                asm("cvt.rn.tf32.f32 %0, %1;" : "=r"(tv) : "f"(acc[i][j]));
                dst[16 * i] = __uint_as_float(tv);
            }
        }
    } else {
        // stage through smem so g_S writes coalesce
        __syncthreads();
#pragma unroll
        for (int i = 0; i < 4; i++)
#pragma unroll
            for (int j = 0; j < 8; j++)
                h0s[(tx + 16 * i) * 129 + (ty + 16 * j)] = acc[i][j];
        __syncthreads();
        for (int idx = t; idx < 64 * 128; idx += 256) {
            int r = idx >> 7, c = idx & 127;
            g_S[p][k0 + r][c] = h0s[r * 129 + c];
        }
    }
}

__global__ void ones_kernel() {
    int i = blockIdx.x * 256 + threadIdx.x;   // 2 * 8192 elems
    int p = i >> 13, k = i & (N_TOK - 1);
    g_B[p][DIM][k] = 1.0f;
}

// ===================== main: C = adj_p[m-tile] @ B_p^T via mma.sync tf32 ====================
// grid (64, 2): x = 128-row m-tile, y = branch. 256 threads = 8 warps, grid 4(M) x 2(N).
// Warp (r,c): rows [32r,32r+32) x cols [72c, 72c+72). Col 128 = rowsum.
__global__ void __launch_bounds__(256, 1) main_kernel(const float* __restrict__ adj_pos,
                                                      const float* __restrict__ adj_neg,
                                                      float* __restrict__ out) {
    extern __shared__ char smc[];
    float* sums = reinterpret_cast<float*>(smc);          // [128] at base
    float* tiles = reinterpret_cast<float*>(smc + 1024);  // 4 stage buffers
    uint32_t sb = smem_u32(smc);

    int tid = threadIdx.x;
    int lane = tid & 31, wid = tid >> 5;
    int g = lane >> 2, t4 = lane & 3;
    int warp_r = wid >> 1, warp_c = wid & 1;
    int m0 = blockIdx.x * 128;
    int p = blockIdx.y;
    const float* Ag = p ? adj_neg : adj_pos;
    const float* Bg = &g_B[p][0][0];

    // ---- stage loader: A 128x32 f32 + B 144x32 f32, padded 144B rows ----
    auto load_stage = [&](int it, int s) {
        int k0 = it * KT;
        uint32_t abuf = sb + 1024 + (uint32_t)s * (STAGE_F * 4);
        uint32_t bbuf = abuf + A_TILE_F * 4;
#pragma unroll
        for (int i = tid; i < 1024; i += 256) {           // A: 128 rows x 8 x 16B
            int r = i >> 3, c = i & 7;
            CP_ASYNC16(abuf + (uint32_t)(r * (ROWF * 4) + c * 16),
                       Ag + (size_t)(m0 + r) * N_TOK + k0 + c * 4);
        }
#pragma unroll
        for (int i = tid; i < 1152; i += 256) {           // B: 144 rows x 8 x 16B
            int r = i >> 3, c = i & 7;
            CP_ASYNC16(bbuf + (uint32_t)(r * (ROWF * 4) + c * 16),
                       Bg + (size_t)r * N_TOK + k0 + c * 4);
        }
        CP_COMMIT();
    };

    float acc[2][9][4];
#pragma unroll
    for (int mt = 0; mt < 2; mt++)
#pragma unroll
        for (int nt = 0; nt < 9; nt++)
#pragma unroll
            for (int q = 0; q < 4; q++) acc[mt][nt][q] = 0.f;

    // row/col bases inside smem tiles (padded rows: ROWF floats each)
    int arow = 32 * warp_r + g;       // A rows: arow + 16*mt (+8)
    int brow = 72 * warp_c + g;       // B rows: brow + 8*nt

    // prologue: 3 stages in flight
    for (int s = 0; s < 3; s++) load_stage(s, s);

    for (int it = 0; it < NITER; it++) {
        int s = it & 3;
        CP_WAITG(2);            // commits so far = it+3 -> stage `it` complete
        __syncthreads();        // all threads see stage `it`; prior compute on buf (it+3)&3 done
        int nit = it + 3;
        if (nit < NITER) load_stage(nit, nit & 3);
        else CP_COMMIT();       // keep group count uniform (empty group)

        const float* As = tiles + s * STAGE_F;
        const float* Bs = As + A_TILE_F;
#pragma unroll
        for (int kk = 0; kk < 4; kk++) {
            int kb = 8 * kk + t4;
            float a[2][4];
#pragma unroll
            for (int mt = 0; mt < 2; mt++) {
                int r = arow + 16 * mt;
                a[mt][0] = As[r * ROWF + kb];
                a[mt][1] = As[(r + 8) * ROWF + kb];
                a[mt][2] = As[r * ROWF + kb + 4];
                a[mt][3] = As[(r + 8) * ROWF + kb + 4];
            }
            float b[9][2];
#pragma unroll
            for (int nt = 0; nt < 9; nt++) {
                int n = brow + 8 * nt;
                b[nt][0] = Bs[n * ROWF + kb];
                b[nt][1] = Bs[n * ROWF + kb + 4];
            }
#pragma unroll
            for (int mt = 0; mt < 2; mt++)
#pragma unroll
                for (int nt = 0; nt < 9; nt++)
                    mma_tf32(acc[mt][nt], a[mt], b[nt]);
        }
    }

    // ---- epilogue ----
    __syncthreads();
    // rowsum lives at global col 128 = warp_c==1, nt=7, 2*t4==0 -> t4==0 lanes, c0/c2 slots
    if (warp_c == 1 && t4 == 0) {
#pragma unroll
        for (int mt = 0; mt < 2; mt++) {
            int row = 32 * warp_r + 16 * mt + g;
            sums[row]     = acc[mt][7][0];
            sums[row + 8] = acc[mt][7][2];
        }
    }
    __syncthreads();

#pragma unroll
    for (int mt = 0; mt < 2; mt++) {
        int row = 32 * warp_r + 16 * mt + g;
        float invA = 1.0f / sums[row];
        float invB = 1.0f / sums[row + 8];
        int mA = m0 + row, mB = mA + 8;
        const float* SA = &g_S[p][mA][0];
        const float* SB = &g_S[p][mB][0];
        float* oA = out + (size_t)mA * 256 + p;
        float* oB = out + (size_t)mB * 256 + p;
#pragma unroll
        for (int nt = 0; nt < 9; nt++) {
            int col = 72 * warp_c + 8 * nt + 2 * t4;
            if (col < DIM) {
                float2 sA = *reinterpret_cast<const float2*>(SA + col);
                float2 sB = *reinterpret_cast<const float2*>(SB + col);
                oA[(col + 0) * 2] = fmaxf(fmaf(acc[mt][nt][0], invA, sA.x), 0.f);
                oA[(col + 1) * 2] = fmaxf(fmaf(acc[mt][nt][1], invA, sA.y), 0.f);
                oB[(col + 0) * 2] = fmaxf(fmaf(acc[mt][nt][2], invB, sB.x), 0.f);
                oB[(col + 1) * 2] = fmaxf(fmaf(acc[mt][nt][3], invB, sB.y), 0.f);
            }
        }
    }
}

// ===================== host =====================
extern "C" void kernel_launch(void* const* d_in, const int* in_sizes, int n_in,
                              void* d_out, int out_size) {
    // metadata order: inputs, adj_pos, adj_neg, h0, WB0, WU0, start, end
    const float* adj_pos = (const float*)d_in[1];
    const float* adj_neg = (const float*)d_in[2];
    const float* h0      = (const float*)d_in[3];
    const float* WB0     = (const float*)d_in[4];
    const float* WU0     = (const float*)d_in[5];
    float* out = (float*)d_out;

    cudaFuncSetAttribute(prep_kernel, cudaFuncAttributeMaxDynamicSharedMemorySize, PREP_SMEM);
    cudaFuncSetAttribute(main_kernel, cudaFuncAttributeMaxDynamicSharedMemorySize, SMEM_MAIN);

    prep_kernel<<<dim3(128, 4), 256, PREP_SMEM>>>(h0, WB0, WU0);
    ones_kernel<<<64, 256>>>();
    main_kernel<<<dim3(64, 2), 256, SMEM_MAIN>>>(adj_pos, adj_neg, out);
}

// round 9
// speedup vs baseline: 1.1222x; 1.1222x over previous
#include <cuda_runtime.h>
#include <cstdint>

// ===================== problem constants =====================
#define N_TOK 8192
#define DIM   128
#define NB    136                 // 128 proj cols + 1 rowsum + 7 pad
#define KT    32                  // fp32 K elems per stage
#define NITER (N_TOK / KT)        // 256
#define ROWF  40                  // floats per padded smem row (160 B; 40%32=8 -> LDS.64 conflict-free)
#define A_TILE_F (128 * ROWF)     // 5120 floats
#define B_TILE_F (NB * ROWF)      // 5440 floats
#define STAGE_F  (A_TILE_F + B_TILE_F)          // 10560 floats = 42240 B
#define SMEM_MAIN (1024 + 4 * STAGE_F * 4)      // 169984 B

// prep tiles: K chunked in 2x64; rows padded to 72 floats (72%32=8 -> conflict-free)
#define PROWF 72
#define PT_F  (128 * PROWF)       // 9216 floats = 36864 B
#define PREP_SMEM (4 * PT_F * 4)  // 147456 B
#define CT_ROW 133                // Ct row pad: 133%32=5, coprime -> conflict-free col reads

// ===================== device scratch ==============
// g_B[p]: rows 0..127 = (h0 @ W[:, :128]^T)^T (tf32-RN), row 128 = ones, 129..135 zero (.bss)
__device__ float g_B[2][NB][N_TOK];
__device__ float g_S[2][N_TOK][DIM];   // self term h0 @ W[:,128:]^T (fp32-grade)

// ===================== helpers =====================
__device__ __forceinline__ uint32_t smem_u32(const void* p) {
    uint32_t a;
    asm("{ .reg .u64 t; cvta.to.shared.u64 t, %1; cvt.u32.u64 %0, t; }" : "=r"(a) : "l"(p));
    return a;
}
__device__ __forceinline__ float tf32rn(float x) {
    uint32_t v;
    asm("cvt.rn.tf32.f32 %0, %1;" : "=r"(v) : "f"(x));
    return __uint_as_float(v);
}

#define CP_ASYNC16(dst, src) \
    asm volatile("cp.async.cg.shared.global [%0], [%1], 16;" :: "r"(dst), "l"(src) : "memory")
#define CP_COMMIT() asm volatile("cp.async.commit_group;" ::: "memory")
#define CP_WAITG(n) asm volatile("cp.async.wait_group %0;" :: "n"(n) : "memory")

// m16n8k8 tf32 MMA (plain sm_80+ PTX path; legal for compute_103)
__device__ __forceinline__ void mma_tf32(float* d, float a0, float a1, float a2, float a3,
                                         float b0, float b1) {
    asm volatile(
        "mma.sync.aligned.m16n8k8.row.col.f32.tf32.tf32.f32 "
        "{%0,%1,%2,%3}, {%4,%5,%6,%7}, {%8,%9}, {%0,%1,%2,%3};"
        : "+f"(d[0]), "+f"(d[1]), "+f"(d[2]), "+f"(d[3])
        : "r"(__float_as_uint(a0)), "r"(__float_as_uint(a1)),
          "r"(__float_as_uint(a2)), "r"(__float_as_uint(a3)),
          "r"(__float_as_uint(b0)), "r"(__float_as_uint(b1)));
}

// ===================== prep: tensor-core, 3-term tf32 split (fp32-grade) =====================
// C[m,n] = h0[m0+m, :] . W[n, half*128 : half*128+128]   (M=128, N=128, K=128)
// half==0 -> G -> g_B[p][n][m] (tf32-RN, transposed), half==1 -> S -> g_S[p][m][n]
// grid (64, 4): x = m-block, y = p*2 + half. 256 threads, 8 warps = 4M x 2N, warp 32x64.
__global__ void __launch_bounds__(256, 1) prep_kernel(const float* __restrict__ h0,
                                                      const float* __restrict__ Wpos,
                                                      const float* __restrict__ Wneg) {
    extern __shared__ float psm[];
    float* Ahi = psm;
    float* Alo = psm + PT_F;
    float* Whi = psm + 2 * PT_F;
    float* Wlo = psm + 3 * PT_F;

    int mode = blockIdx.y;
    int p = mode >> 1, half = mode & 1;
    const float* W = p ? Wneg : Wpos;
    int m0 = blockIdx.x * 128;
    int t = threadIdx.x;
    int lane = t & 31, wid = t >> 5;
    int g = lane >> 2, t4 = lane & 3;
    int warp_r = wid & 3, warp_c = wid >> 2;

    float acc[2][8][4];
#pragma unroll
    for (int mt = 0; mt < 2; mt++)
#pragma unroll
        for (int nt = 0; nt < 8; nt++)
#pragma unroll
            for (int q = 0; q < 4; q++) acc[mt][nt][q] = 0.f;

    for (int kc = 0; kc < 2; kc++) {
        __syncthreads();
        // load + split h0 chunk (rows m0.., cols 64kc..)
        for (int i = t; i < 2048; i += 256) {
            int r = i >> 4, c4 = i & 15;
            float4 v = *reinterpret_cast<const float4*>(h0 + (size_t)(m0 + r) * DIM + kc * 64 + c4 * 4);
            float4 hi, lo;
            hi.x = tf32rn(v.x); lo.x = tf32rn(v.x - hi.x);
            hi.y = tf32rn(v.y); lo.y = tf32rn(v.y - hi.y);
            hi.z = tf32rn(v.z); lo.z = tf32rn(v.z - hi.z);
            hi.w = tf32rn(v.w); lo.w = tf32rn(v.w - hi.w);
            *reinterpret_cast<float4*>(Ahi + r * PROWF + c4 * 4) = hi;
            *reinterpret_cast<float4*>(Alo + r * PROWF + c4 * 4) = lo;
        }
        // load + split W chunk (rows n 0..127, cols half*128 + 64kc ..)
        for (int i = t; i < 2048; i += 256) {
            int r = i >> 4, c4 = i & 15;
            float4 v = *reinterpret_cast<const float4*>(W + (size_t)r * 256 + half * 128 + kc * 64 + c4 * 4);
            float4 hi, lo;
            hi.x = tf32rn(v.x); lo.x = tf32rn(v.x - hi.x);
            hi.y = tf32rn(v.y); lo.y = tf32rn(v.y - hi.y);
            hi.z = tf32rn(v.z); lo.z = tf32rn(v.z - hi.z);
            hi.w = tf32rn(v.w); lo.w = tf32rn(v.w - hi.w);
            *reinterpret_cast<float4*>(Whi + r * PROWF + c4 * 4) = hi;
            *reinterpret_cast<float4*>(Wlo + r * PROWF + c4 * 4) = lo;
        }
        __syncthreads();

        const float2* Ah2 = reinterpret_cast<const float2*>(Ahi);
        const float2* Al2 = reinterpret_cast<const float2*>(Alo);
        const float2* Wh2 = reinterpret_cast<const float2*>(Whi);
        const float2* Wl2 = reinterpret_cast<const float2*>(Wlo);
        int arow = 32 * warp_r + g;
        int brow = 64 * warp_c + g;
#pragma unroll
        for (int kk = 0; kk < 8; kk++) {
            float2 ah0[2], ah1[2], al0[2], al1[2];
#pragma unroll
            for (int mt = 0; mt < 2; mt++) {
                int r = arow + 16 * mt;
                ah0[mt] = Ah2[r * 36 + 4 * kk + t4];
                ah1[mt] = Ah2[(r + 8) * 36 + 4 * kk + t4];
                al0[mt] = Al2[r * 36 + 4 * kk + t4];
                al1[mt] = Al2[(r + 8) * 36 + 4 * kk + t4];
            }
            float2 bh[8], bl[8];
#pragma unroll
            for (int nt = 0; nt < 8; nt++) {
                int n = brow + 8 * nt;
                bh[nt] = Wh2[n * 36 + 4 * kk + t4];
                bl[nt] = Wl2[n * 36 + 4 * kk + t4];
            }
#pragma unroll
            for (int mt = 0; mt < 2; mt++)
#pragma unroll
                for (int nt = 0; nt < 8; nt++) {
                    mma_tf32(acc[mt][nt], ah0[mt].x, ah1[mt].x, ah0[mt].y, ah1[mt].y, bh[nt].x, bh[nt].y);
                    mma_tf32(acc[mt][nt], ah0[mt].x, ah1[mt].x, ah0[mt].y, ah1[mt].y, bl[nt].x, bl[nt].y);
                    mma_tf32(acc[mt][nt], al0[mt].x, al1[mt].x, al0[mt].y, al1[mt].y, bh[nt].x, bh[nt].y);
                }
        }
    }
    __syncthreads();

    // stage C through smem (overlay Ahi/Alo region)
    float* Ct = psm;
#pragma unroll
    for (int mt = 0; mt < 2; mt++) {
        int row = 32 * warp_r + 16 * mt + g;
#pragma unroll
        for (int nt = 0; nt < 8; nt++) {
            int col = 64 * warp_c + 8 * nt + 2 * t4;
            Ct[row * CT_ROW + col]           = acc[mt][nt][0];
            Ct[row * CT_ROW + col + 1]       = acc[mt][nt][1];
            Ct[(row + 8) * CT_ROW + col]     = acc[mt][nt][2];
            Ct[(row + 8) * CT_ROW + col + 1] = acc[mt][nt][3];
        }
    }
    __syncthreads();

    if (half == 0) {
        for (int i = t; i < 16384; i += 256) {          // n-major, m contiguous -> coalesced
            int n = i >> 7, m = i & 127;
            g_B[p][n][m0 + m] = tf32rn(Ct[m * CT_ROW + n]);
        }
    } else {
        for (int i = t; i < 16384; i += 256) {          // m-major, n contiguous -> coalesced
            int m = i >> 7, n = i & 127;
            g_S[p][m0 + m][n] = Ct[m * CT_ROW + n];
        }
    }
}

__global__ void ones_kernel() {
    int i = blockIdx.x * 256 + threadIdx.x;   // 2 * 8192 elems
    int p = i >> 13, k = i & (N_TOK - 1);
    g_B[p][DIM][k] = 1.0f;
}

// ===================== main: C = adj_p[m-tile] @ B_p^T via mma.sync tf32 ====================
// grid (64, 2). 256 thr, 8 warps: warp_r = wid&3 (M 32-rows), warp_c = wid>>2.
// warp_c=0: cols 0..71 (9 n-tiles); warp_c=1: cols 72..135 (8 n-tiles, incl rowsum col 128).
// k-relabel: HW slots (t4, t4+4) <-> global k (8kk+2t4, 8kk+2t4+1) on BOTH A and B -> LDS.64 frags.
__global__ void __launch_bounds__(256, 1) main_kernel(const float* __restrict__ adj_pos,
                                                      const float* __restrict__ adj_neg,
                                                      float* __restrict__ out) {
    extern __shared__ char smc[];
    float* sums = reinterpret_cast<float*>(smc);          // [128]
    float* tiles = reinterpret_cast<float*>(smc + 1024);
    uint32_t sb = smem_u32(smc);

    int tid = threadIdx.x;
    int lane = tid & 31, wid = tid >> 5;
    int g = lane >> 2, t4 = lane & 3;
    int warp_r = wid & 3, warp_c = wid >> 2;
    const int NT = warp_c ? 8 : 9;
    int m0 = blockIdx.x * 128;
    int p = blockIdx.y;
    const float* Ag = p ? adj_neg : adj_pos;
    const float* Bg = &g_B[p][0][0];

    auto load_stage = [&](int it, int s) {
        int k0 = it * KT;
        uint32_t abuf = sb + 1024 + (uint32_t)s * (STAGE_F * 4);
        uint32_t bbuf = abuf + A_TILE_F * 4;
#pragma unroll
        for (int i = tid; i < 1024; i += 256) {           // A: 128 rows x 8 x 16B
            int r = i >> 3, c = i & 7;
            CP_ASYNC16(abuf + (uint32_t)(r * (ROWF * 4) + c * 16),
                       Ag + (size_t)(m0 + r) * N_TOK + k0 + c * 4);
        }
#pragma unroll
        for (int i = tid; i < 1088; i += 256) {           // B: 136 rows x 8 x 16B
            int r = i >> 3, c = i & 7;
            CP_ASYNC16(bbuf + (uint32_t)(r * (ROWF * 4) + c * 16),
                       Bg + (size_t)r * N_TOK + k0 + c * 4);
        }
        CP_COMMIT();
    };

    float acc[2][9][4];
#pragma unroll
    for (int mt = 0; mt < 2; mt++)
#pragma unroll
        for (int nt = 0; nt < 9; nt++)
#pragma unroll
            for (int q = 0; q < 4; q++) acc[mt][nt][q] = 0.f;

    int arow = 32 * warp_r + g;
    int brow = (warp_c ? 72 : 0) + g;

    for (int s = 0; s < 3; s++) load_stage(s, s);

    for (int it = 0; it < NITER; it++) {
        int s = it & 3;
        CP_WAITG(2);            // stage `it` complete
        __syncthreads();
        int nit = it + 3;
        if (nit < NITER) load_stage(nit, nit & 3);
        else CP_COMMIT();       // keep group count uniform

        const float2* As2 = reinterpret_cast<const float2*>(tiles + s * STAGE_F);
        const float2* Bs2 = As2 + A_TILE_F / 2;
#pragma unroll
        for (int kk = 0; kk < 4; kk++) {
            float2 a0[2], a1[2];
#pragma unroll
            for (int mt = 0; mt < 2; mt++) {
                int r = arow + 16 * mt;
                a0[mt] = As2[r * 20 + 4 * kk + t4];        // (k=8kk+2t4, 8kk+2t4+1)
                a1[mt] = As2[(r + 8) * 20 + 4 * kk + t4];
            }
            float2 bf[9];
#pragma unroll
            for (int nt = 0; nt < 9; nt++)
                if (nt < NT) bf[nt] = Bs2[(brow + 8 * nt) * 20 + 4 * kk + t4];
#pragma unroll
            for (int mt = 0; mt < 2; mt++)
#pragma unroll
                for (int nt = 0; nt < 9; nt++)
                    if (nt < NT)
                        mma_tf32(acc[mt][nt], a0[mt].x, a1[mt].x, a0[mt].y, a1[mt].y,
                                 bf[nt].x, bf[nt].y);
        }
    }

    // ---- epilogue ----
    __syncthreads();
    // rowsum = global col 128 = warp_c==1, nt==7, 2t4==0
    if (warp_c == 1 && t4 == 0) {
#pragma unroll
        for (int mt = 0; mt < 2; mt++) {
            int row = 32 * warp_r + 16 * mt + g;
            sums[row]     = acc[mt][7][0];
            sums[row + 8] = acc[mt][7][2];
        }
    }
    __syncthreads();

    int cbase = warp_c ? 72 : 0;
#pragma unroll
    for (int mt = 0; mt < 2; mt++) {
        int row = 32 * warp_r + 16 * mt + g;
        float invA = 1.0f / sums[row];
        float invB = 1.0f / sums[row + 8];
        int mA = m0 + row, mB = mA + 8;
        const float* SA = &g_S[p][mA][0];
        const float* SB = &g_S[p][mB][0];
        float* oA = out + (size_t)mA * 256 + p;
        float* oB = out + (size_t)mB * 256 + p;
#pragma unroll
        for (int nt = 0; nt < 9; nt++) {
            int col = cbase + 8 * nt + 2 * t4;
            if (nt < NT && col < DIM) {
                float2 sA = *reinterpret_cast<const float2*>(SA + col);
                float2 sB = *reinterpret_cast<const float2*>(SB + col);
                oA[(size_t)(col + 0) * 2] = fmaxf(fmaf(acc[mt][nt][0], invA, sA.x), 0.f);
                oA[(size_t)(col + 1) * 2] = fmaxf(fmaf(acc[mt][nt][1], invA, sA.y), 0.f);
                oB[(size_t)(col + 0) * 2] = fmaxf(fmaf(acc[mt][nt][2], invB, sB.x), 0.f);
                oB[(size_t)(col + 1) * 2] = fmaxf(fmaf(acc[mt][nt][3], invB, sB.y), 0.f);
            }
        }
    }
}

// ===================== host =====================
extern "C" void kernel_launch(void* const* d_in, const int* in_sizes, int n_in,
                              void* d_out, int out_size) {
    // metadata order: inputs, adj_pos, adj_neg, h0, WB0, WU0, start, end
    const float* adj_pos = (const float*)d_in[1];
    const float* adj_neg = (const float*)d_in[2];
    const float* h0      = (const float*)d_in[3];
    const float* WB0     = (const float*)d_in[4];
    const float* WU0     = (const float*)d_in[5];
    float* out = (float*)d_out;

    cudaFuncSetAttribute(prep_kernel, cudaFuncAttributeMaxDynamicSharedMemorySize, PREP_SMEM);
    cudaFuncSetAttribute(main_kernel, cudaFuncAttributeMaxDynamicSharedMemorySize, SMEM_MAIN);

    prep_kernel<<<dim3(64, 4), 256, PREP_SMEM>>>(h0, WB0, WU0);
    ones_kernel<<<64, 256>>>();
    main_kernel<<<dim3(64, 2), 256, SMEM_MAIN>>>(adj_pos, adj_neg, out);
}

// round 10
// speedup vs baseline: 1.6712x; 1.4892x over previous
#include <cuda_runtime.h>
#include <cuda_bf16.h>
#include <cstdint>

// ===================== problem constants =====================
#define N_TOK 8192
#define DIM   128
#define NB    136                 // 128 proj cols + 1 rowsum + 7 pad
#define KT    32                  // K elems per stage
#define NITER (N_TOK / KT)        // 256
#define AROWF 48                  // A smem row: 32 f32 data + 16 pad (LDS.128 conflict-free)
#define BROWB 96                  // B smem row bytes: 64 B data + 32 pad (LDS.64 conflict-free)
#define A_TILE_B (128 * AROWF * 4)      // 24576 B
#define B_TILE_B (NB * BROWB)           // 13056 B
#define STAGE_B  (A_TILE_B + B_TILE_B)  // 37632 B
#define SMEM_MAIN (1024 + 4 * STAGE_B)  // 151552 B

// prep tiles (unchanged from R9)
#define PROWF 72
#define PT_F  (128 * PROWF)
#define PREP_SMEM (4 * PT_F * 4)  // 147456 B
#define CT_ROW 133

// ===================== device scratch ==============
// g_B[p]: rows 0..127 = (h0 @ W[:, :128]^T)^T in bf16, row 128 = ones, 129..135 zero (.bss)
__device__ __nv_bfloat16 g_B[2][NB][N_TOK];
__device__ float g_S[2][N_TOK][DIM];   // self term h0 @ W[:,128:]^T (fp32-grade)

// ===================== helpers =====================
__device__ __forceinline__ uint32_t smem_u32(const void* p) {
    uint32_t a;
    asm("{ .reg .u64 t; cvta.to.shared.u64 t, %1; cvt.u32.u64 %0, t; }" : "=r"(a) : "l"(p));
    return a;
}
__device__ __forceinline__ float tf32rn(float x) {
    uint32_t v;
    asm("cvt.rn.tf32.f32 %0, %1;" : "=r"(v) : "f"(x));
    return __uint_as_float(v);
}
__device__ __forceinline__ uint32_t packbf(float hi, float lo) {   // {hi | lo} bf16x2
    uint32_t r;
    asm("cvt.rn.bf16x2.f32 %0, %1, %2;" : "=r"(r) : "f"(hi), "f"(lo));
    return r;
}

#define CP_ASYNC16(dst, src) \
    asm volatile("cp.async.cg.shared.global [%0], [%1], 16;" :: "r"(dst), "l"(src) : "memory")
#define CP_COMMIT() asm volatile("cp.async.commit_group;" ::: "memory")
#define CP_WAITG(n) asm volatile("cp.async.wait_group %0;" :: "n"(n) : "memory")

// m16n8k8 tf32 (prep) — plain sm_80+ PTX
__device__ __forceinline__ void mma_tf32(float* d, float a0, float a1, float a2, float a3,
                                         float b0, float b1) {
    asm volatile(
        "mma.sync.aligned.m16n8k8.row.col.f32.tf32.tf32.f32 "
        "{%0,%1,%2,%3}, {%4,%5,%6,%7}, {%8,%9}, {%0,%1,%2,%3};"
        : "+f"(d[0]), "+f"(d[1]), "+f"(d[2]), "+f"(d[3])
        : "r"(__float_as_uint(a0)), "r"(__float_as_uint(a1)),
          "r"(__float_as_uint(a2)), "r"(__float_as_uint(a3)),
          "r"(__float_as_uint(b0)), "r"(__float_as_uint(b1)));
}
// m16n8k16 bf16 (main) — plain sm_80+ PTX
__device__ __forceinline__ void mma_bf16(float* d, uint32_t a0, uint32_t a1, uint32_t a2,
                                         uint32_t a3, uint32_t b0, uint32_t b1) {
    asm volatile(
        "mma.sync.aligned.m16n8k16.row.col.f32.bf16.bf16.f32 "
        "{%0,%1,%2,%3}, {%4,%5,%6,%7}, {%8,%9}, {%0,%1,%2,%3};"
        : "+f"(d[0]), "+f"(d[1]), "+f"(d[2]), "+f"(d[3])
        : "r"(a0), "r"(a1), "r"(a2), "r"(a3), "r"(b0), "r"(b1));
}

// ===================== prep: tensor-core, 3-term tf32 split (fp32-grade) =====================
// C[m,n] = h0[m0+m, :] . W[n, half*128 : +128]; half0 -> g_B (bf16, transposed), half1 -> g_S
__global__ void __launch_bounds__(256, 1) prep_kernel(const float* __restrict__ h0,
                                                      const float* __restrict__ Wpos,
                                                      const float* __restrict__ Wneg) {
    extern __shared__ float psm[];
    float* Ahi = psm;
    float* Alo = psm + PT_F;
    float* Whi = psm + 2 * PT_F;
    float* Wlo = psm + 3 * PT_F;

    int mode = blockIdx.y;
    int p = mode >> 1, half = mode & 1;
    const float* W = p ? Wneg : Wpos;
    int m0 = blockIdx.x * 128;
    int t = threadIdx.x;
    int lane = t & 31, wid = t >> 5;
    int g = lane >> 2, t4 = lane & 3;
    int warp_r = wid & 3, warp_c = wid >> 2;

    float acc[2][8][4];
#pragma unroll
    for (int mt = 0; mt < 2; mt++)
#pragma unroll
        for (int nt = 0; nt < 8; nt++)
#pragma unroll
            for (int q = 0; q < 4; q++) acc[mt][nt][q] = 0.f;

    for (int kc = 0; kc < 2; kc++) {
        __syncthreads();
        for (int i = t; i < 2048; i += 256) {
            int r = i >> 4, c4 = i & 15;
            float4 v = *reinterpret_cast<const float4*>(h0 + (size_t)(m0 + r) * DIM + kc * 64 + c4 * 4);
            float4 hi, lo;
            hi.x = tf32rn(v.x); lo.x = tf32rn(v.x - hi.x);
            hi.y = tf32rn(v.y); lo.y = tf32rn(v.y - hi.y);
            hi.z = tf32rn(v.z); lo.z = tf32rn(v.z - hi.z);
            hi.w = tf32rn(v.w); lo.w = tf32rn(v.w - hi.w);
            *reinterpret_cast<float4*>(Ahi + r * PROWF + c4 * 4) = hi;
            *reinterpret_cast<float4*>(Alo + r * PROWF + c4 * 4) = lo;
        }
        for (int i = t; i < 2048; i += 256) {
            int r = i >> 4, c4 = i & 15;
            float4 v = *reinterpret_cast<const float4*>(W + (size_t)r * 256 + half * 128 + kc * 64 + c4 * 4);
            float4 hi, lo;
            hi.x = tf32rn(v.x); lo.x = tf32rn(v.x - hi.x);
            hi.y = tf32rn(v.y); lo.y = tf32rn(v.y - hi.y);
            hi.z = tf32rn(v.z); lo.z = tf32rn(v.z - hi.z);
            hi.w = tf32rn(v.w); lo.w = tf32rn(v.w - hi.w);
            *reinterpret_cast<float4*>(Whi + r * PROWF + c4 * 4) = hi;
            *reinterpret_cast<float4*>(Wlo + r * PROWF + c4 * 4) = lo;
        }
        __syncthreads();

        const float2* Ah2 = reinterpret_cast<const float2*>(Ahi);
        const float2* Al2 = reinterpret_cast<const float2*>(Alo);
        const float2* Wh2 = reinterpret_cast<const float2*>(Whi);
        const float2* Wl2 = reinterpret_cast<const float2*>(Wlo);
        int arow = 32 * warp_r + g;
        int brow = 64 * warp_c + g;
#pragma unroll
        for (int kk = 0; kk < 8; kk++) {
            float2 ah0[2], ah1[2], al0[2], al1[2];
#pragma unroll
            for (int mt = 0; mt < 2; mt++) {
                int r = arow + 16 * mt;
                ah0[mt] = Ah2[r * 36 + 4 * kk + t4];
                ah1[mt] = Ah2[(r + 8) * 36 + 4 * kk + t4];
                al0[mt] = Al2[r * 36 + 4 * kk + t4];
                al1[mt] = Al2[(r + 8) * 36 + 4 * kk + t4];
            }
            float2 bh[8], bl[8];
#pragma unroll
            for (int nt = 0; nt < 8; nt++) {
                int n = brow + 8 * nt;
                bh[nt] = Wh2[n * 36 + 4 * kk + t4];
                bl[nt] = Wl2[n * 36 + 4 * kk + t4];
            }
#pragma unroll
            for (int mt = 0; mt < 2; mt++)
#pragma unroll
                for (int nt = 0; nt < 8; nt++) {
                    mma_tf32(acc[mt][nt], ah0[mt].x, ah1[mt].x, ah0[mt].y, ah1[mt].y, bh[nt].x, bh[nt].y);
                    mma_tf32(acc[mt][nt], ah0[mt].x, ah1[mt].x, ah0[mt].y, ah1[mt].y, bl[nt].x, bl[nt].y);
                    mma_tf32(acc[mt][nt], al0[mt].x, al1[mt].x, al0[mt].y, al1[mt].y, bh[nt].x, bh[nt].y);
                }
        }
    }
    __syncthreads();

    float* Ct = psm;
#pragma unroll
    for (int mt = 0; mt < 2; mt++) {
        int row = 32 * warp_r + 16 * mt + g;
#pragma unroll
        for (int nt = 0; nt < 8; nt++) {
            int col = 64 * warp_c + 8 * nt + 2 * t4;
            Ct[row * CT_ROW + col]           = acc[mt][nt][0];
            Ct[row * CT_ROW + col + 1]       = acc[mt][nt][1];
            Ct[(row + 8) * CT_ROW + col]     = acc[mt][nt][2];
            Ct[(row + 8) * CT_ROW + col + 1] = acc[mt][nt][3];
        }
    }
    __syncthreads();

    if (half == 0) {
        for (int i = t; i < 16384; i += 256) {          // n-major, m contiguous -> coalesced
            int n = i >> 7, m = i & 127;
            g_B[p][n][m0 + m] = __float2bfloat16(Ct[m * CT_ROW + n]);
        }
    } else {
        for (int i = t; i < 16384; i += 256) {
            int m = i >> 7, n = i & 127;
            g_S[p][m0 + m][n] = Ct[m * CT_ROW + n];
        }
    }
}

__global__ void ones_kernel() {
    int i = blockIdx.x * 256 + threadIdx.x;   // 2 * 8192 elems
    int p = i >> 13, k = i & (N_TOK - 1);
    g_B[p][DIM][k] = __float2bfloat16(1.0f);
}

// ===================== main: C = adj_p[m-tile] @ B_p^T via mma.sync bf16 m16n8k16 ============
// grid (64, 2). 256 thr, 8 warps: warp_r = wid&3, warp_c = wid>>2 (9 / 8 n-tiles).
// k-relabel: HW k-slots {2t4,2t4+1,2t4+8,2t4+9} <-> global k {4t4..4t4+3} on both operands:
//   A frag = LDS.128 float4 (fp32, cvt to bf16x2 in regs), B frag = LDS.64 (4 contig bf16).
__global__ void __launch_bounds__(256, 1) main_kernel(const float* __restrict__ adj_pos,
                                                      const float* __restrict__ adj_neg,
                                                      float* __restrict__ out) {
    extern __shared__ char smc[];
    float* sums = reinterpret_cast<float*>(smc);          // [128]
    char* tiles = smc + 1024;
    uint32_t sb = smem_u32(smc);

    int tid = threadIdx.x;
    int lane = tid & 31, wid = tid >> 5;
    int g = lane >> 2, t4 = lane & 3;
    int warp_r = wid & 3, warp_c = wid >> 2;
    const int NT = warp_c ? 8 : 9;
    int m0 = blockIdx.x * 128;
    int p = blockIdx.y;
    const float* Ag = p ? adj_neg : adj_pos;
    const __nv_bfloat16* Bg = &g_B[p][0][0];

    auto load_stage = [&](int it, int s) {
        int k0 = it * KT;
        uint32_t abuf = sb + 1024 + (uint32_t)s * STAGE_B;
        uint32_t bbuf = abuf + A_TILE_B;
#pragma unroll
        for (int i = tid; i < 1024; i += 256) {           // A: 128 rows x 8 x 16B (f32)
            int r = i >> 3, c = i & 7;
            CP_ASYNC16(abuf + (uint32_t)(r * (AROWF * 4) + c * 16),
                       Ag + (size_t)(m0 + r) * N_TOK + k0 + c * 4);
        }
#pragma unroll
        for (int i = tid; i < 544; i += 256) {            // B: 136 rows x 4 x 16B (bf16)
            int r = i >> 2, c = i & 3;
            CP_ASYNC16(bbuf + (uint32_t)(r * BROWB + c * 16),
                       Bg + (size_t)r * N_TOK + k0 + c * 8);
        }
        CP_COMMIT();
    };

    float acc[2][9][4];
#pragma unroll
    for (int mt = 0; mt < 2; mt++)
#pragma unroll
        for (int nt = 0; nt < 9; nt++)
#pragma unroll
            for (int q = 0; q < 4; q++) acc[mt][nt][q] = 0.f;

    int arow = 32 * warp_r + g;
    int brow = (warp_c ? 72 : 0) + g;

    for (int s = 0; s < 3; s++) load_stage(s, s);

    for (int it = 0; it < NITER; it++) {
        int s = it & 3;
        CP_WAITG(2);            // stage `it` complete
        __syncthreads();
        int nit = it + 3;
        if (nit < NITER) load_stage(nit, nit & 3);
        else CP_COMMIT();       // keep group count uniform

        const float4* As4 = reinterpret_cast<const float4*>(tiles + (size_t)s * STAGE_B);
        const uint2* Bs2 = reinterpret_cast<const uint2*>(tiles + (size_t)s * STAGE_B + A_TILE_B);
#pragma unroll
        for (int kk = 0; kk < 2; kk++) {
            // A frags: float4 at (row, global k 16kk + 4t4), AROWF/4 = 12 float4s per row
            uint32_t a[2][4];
#pragma unroll
            for (int mt = 0; mt < 2; mt++) {
                int r = arow + 16 * mt;
                float4 v0 = As4[r * 12 + 4 * kk + t4];
                float4 v1 = As4[(r + 8) * 12 + 4 * kk + t4];
                a[mt][0] = packbf(v0.y, v0.x);   // (g,   k0 k1)
                a[mt][1] = packbf(v1.y, v1.x);   // (g+8, k0 k1)
                a[mt][2] = packbf(v0.w, v0.z);   // (g,   k2 k3)
                a[mt][3] = packbf(v1.w, v1.z);   // (g+8, k2 k3)
            }
            // B frags: uint2 at (n, global k), BROWB/8 = 12 uint2s per row
            uint2 bf[9];
#pragma unroll
            for (int nt = 0; nt < 9; nt++)
                if (nt < NT) bf[nt] = Bs2[(brow + 8 * nt) * 12 + 4 * kk + t4];
#pragma unroll
            for (int mt = 0; mt < 2; mt++)
#pragma unroll
                for (int nt = 0; nt < 9; nt++)
                    if (nt < NT)
                        mma_bf16(acc[mt][nt], a[mt][0], a[mt][1], a[mt][2], a[mt][3],
                                 bf[nt].x, bf[nt].y);
        }
    }

    // ---- epilogue ----
    __syncthreads();
    // rowsum = global col 128 = warp_c==1, nt==7, 2t4==0
    if (warp_c == 1 && t4 == 0) {
#pragma unroll
        for (int mt = 0; mt < 2; mt++) {
            int row = 32 * warp_r + 16 * mt + g;
            sums[row]     = acc[mt][7][0];
            sums[row + 8] = acc[mt][7][2];
        }
    }
    __syncthreads();

    int cbase = warp_c ? 72 : 0;
#pragma unroll
    for (int mt = 0; mt < 2; mt++) {
        int row = 32 * warp_r + 16 * mt + g;
        float invA = 1.0f / sums[row];
        float invB = 1.0f / sums[row + 8];
        int mA = m0 + row, mB = mA + 8;
        const float* SA = &g_S[p][mA][0];
        const float* SB = &g_S[p][mB][0];
        float* oA = out + (size_t)mA * 256 + p;
        float* oB = out + (size_t)mB * 256 + p;
#pragma unroll
        for (int nt = 0; nt < 9; nt++) {
            int col = cbase + 8 * nt + 2 * t4;
            if (nt < NT && col < DIM) {
                float2 sA = *reinterpret_cast<const float2*>(SA + col);
                float2 sB = *reinterpret_cast<const float2*>(SB + col);
                oA[(size_t)(col + 0) * 2] = fmaxf(fmaf(acc[mt][nt][0], invA, sA.x), 0.f);
                oA[(size_t)(col + 1) * 2] = fmaxf(fmaf(acc[mt][nt][1], invA, sA.y), 0.f);
                oB[(size_t)(col + 0) * 2] = fmaxf(fmaf(acc[mt][nt][2], invB, sB.x), 0.f);
                oB[(size_t)(col + 1) * 2] = fmaxf(fmaf(acc[mt][nt][3], invB, sB.y), 0.f);
            }
        }
    }
}

// ===================== host =====================
extern "C" void kernel_launch(void* const* d_in, const int* in_sizes, int n_in,
                              void* d_out, int out_size) {
    // metadata order: inputs, adj_pos, adj_neg, h0, WB0, WU0, start, end
    const float* adj_pos = (const float*)d_in[1];
    const float* adj_neg = (const float*)d_in[2];
    const float* h0      = (const float*)d_in[3];
    const float* WB0     = (const float*)d_in[4];
    const float* WU0     = (const float*)d_in[5];
    float* out = (float*)d_out;

    cudaFuncSetAttribute(prep_kernel, cudaFuncAttributeMaxDynamicSharedMemorySize, PREP_SMEM);
    cudaFuncSetAttribute(main_kernel, cudaFuncAttributeMaxDynamicSharedMemorySize, SMEM_MAIN);

    prep_kernel<<<dim3(64, 4), 256, PREP_SMEM>>>(h0, WB0, WU0);
    ones_kernel<<<64, 256>>>();
    main_kernel<<<dim3(64, 2), 256, SMEM_MAIN>>>(adj_pos, adj_neg, out);
}